// round 2
// baseline (speedup 1.0000x reference)
#include <cuda_runtime.h>
#include <cuda_bf16.h>

// Problem constants (fixed by setup_inputs)
#define BATCH 32
#define TSEQ  1024
#define DIM   512
#define NMAX  500000
#define MAXK  64

#define FULLMASK 0xffffffffu
#define NEG_BIG (-3.0e38f)

// ---------------- device scratch (no allocations allowed) ----------------
__device__ float g_part[BATCH * 8 * DIM];      // partial sums for mean pooling
__device__ float g_query[BATCH * DIM];         // router query
__device__ float g_scores[BATCH * NMAX];       // 64 MB score matrix
__device__ float g_topv[BATCH * MAXK];         // sorted top-64 values per row
__device__ int   g_topi[BATCH * MAXK];         // matching indices

// ---------------- kernel 1: partial mean over T ----------------
__global__ void k_pool_partial(const float* __restrict__ hidden) {
    int b = blockIdx.x >> 3;
    int chunk = blockIdx.x & 7;
    int tid = threadIdx.x;
    const float* base = hidden + ((size_t)b * TSEQ + chunk * 128) * DIM;
    float a0 = 0.f, a1 = 0.f;
#pragma unroll 4
    for (int t = 0; t < 128; ++t) {
        a0 += base[t * DIM + tid];
        a1 += base[t * DIM + tid + 256];
    }
    g_part[(b * 8 + chunk) * DIM + tid]       = a0;
    g_part[(b * 8 + chunk) * DIM + tid + 256] = a1;
}

// ---------------- kernel 2: finalize pooled mean + query = pooled @ W + b ----------------
__global__ void k_query(const float* __restrict__ W, const float* __restrict__ bias) {
    int b = blockIdx.x;
    int j = threadIdx.x;
    __shared__ float sp[DIM];
    float s = 0.f;
#pragma unroll
    for (int c = 0; c < 8; ++c) s += g_part[(b * 8 + c) * DIM + j];
    sp[j] = s * (1.0f / (float)TSEQ);
    __syncthreads();
    float q = bias[j];
#pragma unroll 8
    for (int d = 0; d < DIM; ++d) {
        q += sp[d] * W[d * DIM + j];
    }
    g_query[b * DIM + j] = q;
}

// ---------------- kernel 3: scores = (query @ keys^T) / sqrt(D) ----------------
#define BN 256          // keys per block
#define BK 128          // k-extent per smem tile
#define KSTRIDE (BK + 2)

__device__ __forceinline__ unsigned long long f32x2_fma(unsigned long long a,
                                                        unsigned long long b,
                                                        unsigned long long c) {
    unsigned long long d;
    asm("fma.rn.f32x2 %0, %1, %2, %3;" : "=l"(d) : "l"(a), "l"(b), "l"(c));
    return d;
}

__global__ void __launch_bounds__(256, 1)
k_scores(const float* __restrict__ keys, int N) {
    extern __shared__ float smem[];
    float* qs = smem;                 // [32][512] full query matrix
    float* ks = smem + BATCH * DIM;   // [BN][KSTRIDE]

    int tid = threadIdx.x;
    int tx = tid & 63;       // key group (4 keys, stride 64)
    int ty = tid >> 6;       // batch group (8 batches)
    int n0 = blockIdx.x * BN;

#pragma unroll
    for (int i = 0; i < (BATCH * DIM) / 256; ++i)
        qs[tid + i * 256] = g_query[tid + i * 256];

    unsigned long long acc[8][4];
#pragma unroll
    for (int i = 0; i < 8; ++i)
#pragma unroll
        for (int j = 0; j < 4; ++j) acc[i][j] = 0ull;

    for (int kt = 0; kt < DIM / BK; ++kt) {
        __syncthreads();
#pragma unroll
        for (int it = 0; it < 32; ++it) {
            int f = tid + it * 256;
            int key = f >> 5;          // BK/4 = 32 float4 per key
            int kq = f & 31;
            int gk = n0 + key;
            float4 v;
            if (gk < N) {
                v = *reinterpret_cast<const float4*>(&keys[(size_t)gk * DIM + kt * BK + kq * 4]);
            } else {
                v = make_float4(0.f, 0.f, 0.f, 0.f);
            }
            float2* dst = reinterpret_cast<float2*>(&ks[key * KSTRIDE + kq * 4]);
            dst[0] = make_float2(v.x, v.y);
            dst[1] = make_float2(v.z, v.w);
        }
        __syncthreads();

#pragma unroll 4
        for (int kp = 0; kp < BK; kp += 2) {
            unsigned long long kv[4], qv[8];
#pragma unroll
            for (int j = 0; j < 4; ++j)
                kv[j] = *reinterpret_cast<const unsigned long long*>(&ks[(tx + j * 64) * KSTRIDE + kp]);
#pragma unroll
            for (int i = 0; i < 8; ++i)
                qv[i] = *reinterpret_cast<const unsigned long long*>(&qs[(ty * 8 + i) * DIM + kt * BK + kp]);
#pragma unroll
            for (int i = 0; i < 8; ++i)
#pragma unroll
                for (int j = 0; j < 4; ++j)
                    acc[i][j] = f32x2_fma(qv[i], kv[j], acc[i][j]);
        }
    }

    const float scale = 1.0f / sqrtf((float)DIM);
#pragma unroll
    for (int i = 0; i < 8; ++i) {
        int b = ty * 8 + i;
#pragma unroll
        for (int j = 0; j < 4; ++j) {
            int n = n0 + tx + j * 64;
            if (n < N) {
                unsigned long long u = acc[i][j];
                float lo = __uint_as_float((unsigned)(u & 0xffffffffull));
                float hi = __uint_as_float((unsigned)(u >> 32));
                g_scores[(size_t)b * N + n] = (lo + hi) * scale;
            }
        }
    }
}

// ---------------- kernel 4: exact top-64 per row ----------------
// grid 32 blocks (one per row), 1024 threads (32 warps).
// NOTE: trip count is warp-UNIFORM (fixes the round-1 collective deadlock).
__device__ __forceinline__ float warp_min32(float v) {
#pragma unroll
    for (int o = 16; o; o >>= 1) v = fminf(v, __shfl_xor_sync(FULLMASK, v, o));
    return v;
}

__global__ void __launch_bounds__(1024)
k_topk(int N) {
    int row = blockIdx.x;
    int tid = threadIdx.x;
    int lane = tid & 31;
    int wid = tid >> 5;

    const float* S = g_scores + (size_t)row * N;
    const float4* S4 = reinterpret_cast<const float4*>(S);
    int N4 = N >> 2;                     // full float4 chunks
    int iters = (((N + 3) >> 2) + 1023) >> 10;  // UNIFORM trip count over ceil(N/4)

    float v0 = NEG_BIG, v1 = NEG_BIG;
    int i0 = 0, i1 = 0;
    float thr = NEG_BIG;

    for (int it = 0; it < iters; ++it) {
        int f = tid + (it << 10);
        int base = f << 2;
        float a0, a1, a2, a3;
        if (f < N4) {
            float4 x = S4[f];
            a0 = x.x; a1 = x.y; a2 = x.z; a3 = x.w;
        } else {
            a0 = (base + 0 < N) ? S[base + 0] : NEG_BIG;
            a1 = (base + 1 < N) ? S[base + 1] : NEG_BIG;
            a2 = (base + 2 < N) ? S[base + 2] : NEG_BIG;
            a3 = (base + 3 < N) ? S[base + 3] : NEG_BIG;
        }
        unsigned pm = (unsigned)(a0 > thr) | ((unsigned)(a1 > thr) << 1) |
                      ((unsigned)(a2 > thr) << 2) | ((unsigned)(a3 > thr) << 3);
        while (__any_sync(FULLMASK, pm != 0)) {
            int c = __ffs(pm) - 1; // valid only where pm != 0
            float cv = (c == 0) ? a0 : (c == 1) ? a1 : (c == 2) ? a2 : a3;
            int ci = base + c;
            unsigned ball = __ballot_sync(FULLMASK, pm != 0);
            int src = __ffs(ball) - 1;
            float cand = __shfl_sync(FULLMASK, cv, src);
            int candi = __shfl_sync(FULLMASK, ci, src);
            if (lane == src) pm &= pm - 1;
            if (cand > thr) {
                float mn = fminf(v0, v1);
                float wmn = warp_min32(mn);
                unsigned who = __ballot_sync(FULLMASK, mn == wmn);
                int wl = __ffs(who) - 1;
                if (lane == wl) {
                    if (v0 <= v1) { v0 = cand; i0 = candi; }
                    else          { v1 = cand; i1 = candi; }
                }
                thr = warp_min32(fminf(v0, v1));
            }
            if (pm) {
                if ((pm & 1u) && a0 <= thr) pm &= ~1u;
                if ((pm & 2u) && a1 <= thr) pm &= ~2u;
                if ((pm & 4u) && a2 <= thr) pm &= ~4u;
                if ((pm & 8u) && a3 <= thr) pm &= ~8u;
            }
        }
    }

    __shared__ float sv[2048];
    __shared__ int   si[2048];
    __shared__ float wv[32];
    __shared__ int   wp[32];
    sv[wid * 64 + lane]      = v0;  si[wid * 64 + lane]      = i0;
    sv[wid * 64 + 32 + lane] = v1;  si[wid * 64 + 32 + lane] = i1;
    __syncthreads();

    for (int j = 0; j < MAXK; ++j) {
        float bv = sv[wid * 64 + lane];      int bp = wid * 64 + lane;
        float ov = sv[wid * 64 + 32 + lane]; int op = wid * 64 + 32 + lane;
        if (ov > bv || (ov == bv && op < bp)) { bv = ov; bp = op; }
#pragma unroll
        for (int o = 16; o; o >>= 1) {
            float xv = __shfl_xor_sync(FULLMASK, bv, o);
            int   xp = __shfl_xor_sync(FULLMASK, bp, o);
            if (xv > bv || (xv == bv && xp < bp)) { bv = xv; bp = xp; }
        }
        if (lane == 0) { wv[wid] = bv; wp[wid] = bp; }
        __syncthreads();
        if (wid == 0) {
            float cv2 = wv[lane]; int cp2 = wp[lane];
#pragma unroll
            for (int o = 16; o; o >>= 1) {
                float xv = __shfl_xor_sync(FULLMASK, cv2, o);
                int   xp = __shfl_xor_sync(FULLMASK, cp2, o);
                if (xv > cv2 || (xv == cv2 && xp < cp2)) { cv2 = xv; cp2 = xp; }
            }
            if (lane == 0) {
                g_topv[row * MAXK + j] = cv2;
                g_topi[row * MAXK + j] = si[cp2];
                sv[cp2] = NEG_BIG;
            }
        }
        __syncthreads();
    }
}

// ---------------- kernel 5: softmax(top-kd) + gather + weighted sum ----------------
__global__ void k_aggregate(const float* __restrict__ P,
                            const int* __restrict__ kdyn,
                            float* __restrict__ out) {
    int row = blockIdx.x;
    int tid = threadIdx.x;
    __shared__ float ws[MAXK];
    __shared__ int   idx[MAXK];
    __shared__ float s_inv;

    int kd = *kdyn;
    kd = kd < 0 ? 0 : (kd > MAXK ? MAXK : kd);

    if (tid < MAXK) {
        float v = g_topv[row * MAXK + tid];
        idx[tid] = g_topi[row * MAXK + tid];
        float m = (kd > 0) ? g_topv[row * MAXK] : -1e9f;
        float mv = (tid < kd) ? v : -1e9f;
        ws[tid] = expf(mv - m);
    }
    __syncthreads();
    if (tid == 0) {
        float s = 0.f;
#pragma unroll
        for (int j = 0; j < MAXK; ++j) s += ws[j];
        s_inv = 1.0f / s;
    }
    __syncthreads();

    float a = 0.f;
#pragma unroll 4
    for (int j = 0; j < MAXK; ++j) {
        float w = ws[j];
        if (w != 0.f) a += w * P[(size_t)idx[j] * DIM + tid];
    }
    out[row * DIM + tid] = a * s_inv;
}

// ---------------- launcher ----------------
extern "C" void kernel_launch(void* const* d_in, const int* in_sizes, int n_in,
                              void* d_out, int out_size) {
    const float* hidden      = (const float*)d_in[0];
    const float* pool_params = (const float*)d_in[1];
    const float* pool_keys   = (const float*)d_in[2];
    const float* W           = (const float*)d_in[3];
    const float* bias        = (const float*)d_in[4];
    const int*   k_dynamic   = (const int*)d_in[5];
    float* out = (float*)d_out;

    int N = in_sizes[2] / DIM;   // number of pool vectors

    static const size_t SMEM3 = (size_t)(BATCH * DIM + BN * KSTRIDE) * sizeof(float);
    cudaFuncSetAttribute(k_scores, cudaFuncAttributeMaxDynamicSharedMemorySize, (int)SMEM3);

    k_pool_partial<<<BATCH * 8, 256>>>(hidden);
    k_query<<<BATCH, DIM>>>(W, bias);
    int nblk = (N + BN - 1) / BN;
    k_scores<<<nblk, 256, SMEM3>>>(pool_keys, N);
    k_topk<<<BATCH, 1024>>>(N);
    k_aggregate<<<BATCH, DIM>>>(pool_params, k_dynamic, out);
}